// round 2
// baseline (speedup 1.0000x reference)
#include <cuda_runtime.h>
#include <math_constants.h>

#define BB 128
#define TT 2048
#define HH 256
#define OUTD 128

#define NCHUNK 16                       // chunks per batch
#define ROWS_PER_CTA (TT / NCHUNK)      // 128
#define K1_THREADS 128                  // 4 warps
#define K1_WARPS (K1_THREADS / 32)
#define ROWS_PER_WARP (ROWS_PER_CTA / K1_WARPS)  // 32
#define RCHUNK 4                        // rows per inner chunk
#define NPART (BB * NCHUNK)             // 2048 partials

// Global scratch (allocation-free per harness rules)
__device__ float g_v[BB * HH];          // v_b = W_score @ h_t[b]
__device__ float g_m[NPART];
__device__ float g_z[NPART];
__device__ float g_acc[NPART * HH];     // 2MB

// ---------------------------------------------------------------------------
// kernel0: v[b,h] = sum_k W_score[h,k] * hidden[b,T-1,k]     grid=BB, 128 thr
// ---------------------------------------------------------------------------
__global__ __launch_bounds__(128)
void k0_compute_v(const float* __restrict__ hidden,
                  const float* __restrict__ Wscore)
{
    __shared__ float s_ht[HH];
    const int b = blockIdx.x;
    const int tid = threadIdx.x, w = tid >> 5, lane = tid & 31;
    const float* ht = hidden + ((size_t)b * TT + (TT - 1)) * HH;
    s_ht[tid] = ht[tid];
    s_ht[tid + 128] = ht[tid + 128];
    __syncthreads();

    // warp w covers rows h = 64w .. 64w+63
    #pragma unroll
    for (int j = 0; j < 64; j++) {
        const int h = w * 64 + j;
        const float* row = Wscore + h * HH;
        float p = 0.f;
        #pragma unroll
        for (int k = lane; k < HH; k += 32) p += row[k] * s_ht[k];
        #pragma unroll
        for (int off = 16; off; off >>= 1) p += __shfl_xor_sync(0xffffffffu, p, off);
        if (lane == 0) g_v[b * HH + h] = p;
    }
}

// ---------------------------------------------------------------------------
// kernel1: streamed online-softmax partials per (batch, chunk)
//          grid = BB*NCHUNK, 128 thr, <=64 regs (8 CTAs/SM)
// ---------------------------------------------------------------------------
__global__ __launch_bounds__(K1_THREADS, 8)
void k1_stream(const float* __restrict__ hidden)
{
    __shared__ float s_wm[K1_WARPS];
    __shared__ float s_wz[K1_WARPS];
    __shared__ float s_acc[K1_WARPS][HH];

    const int cta   = blockIdx.x;
    const int b     = cta >> 4;          // / NCHUNK
    const int chunk = cta & (NCHUNK - 1);
    const int tid   = threadIdx.x, w = tid >> 5, lane = tid & 31;

    // per-lane v slice (channels 8*lane .. 8*lane+7)
    const float* vp = g_v + b * HH + lane * 8;
    const float4 v0 = *(const float4*)(vp);
    const float4 v1 = *(const float4*)(vp + 4);

    float  m = -CUDART_INF_F, Z = 0.f;
    float4 a0 = make_float4(0.f, 0.f, 0.f, 0.f);
    float4 a1 = make_float4(0.f, 0.f, 0.f, 0.f);

    const float* rowp = hidden
        + ((size_t)b * TT + chunk * ROWS_PER_CTA + w * ROWS_PER_WARP) * HH
        + lane * 8;

    for (int c = 0; c < ROWS_PER_WARP / RCHUNK; c++) {
        // batch 8 independent 16B loads (MLP)
        float4 x[RCHUNK][2];
        #pragma unroll
        for (int r = 0; r < RCHUNK; r++) {
            x[r][0] = *(const float4*)(rowp + r * HH);
            x[r][1] = *(const float4*)(rowp + r * HH + 4);
        }
        rowp += RCHUNK * HH;

        // 4 independent partial dots
        float s[RCHUNK];
        #pragma unroll
        for (int r = 0; r < RCHUNK; r++) {
            s[r] = x[r][0].x * v0.x + x[r][0].y * v0.y + x[r][0].z * v0.z + x[r][0].w * v0.w
                 + x[r][1].x * v1.x + x[r][1].y * v1.y + x[r][1].z * v1.z + x[r][1].w * v1.w;
        }
        // interleaved shuffle reductions (4 independent chains pipeline)
        #pragma unroll
        for (int off = 16; off; off >>= 1) {
            #pragma unroll
            for (int r = 0; r < RCHUNK; r++)
                s[r] += __shfl_xor_sync(0xffffffffu, s[r], off);
        }

        // one rescale per chunk (warp-uniform)
        float mc = fmaxf(fmaxf(s[0], s[1]), fmaxf(s[2], s[3]));
        if (mc > m) {
            const float sc = __expf(m - mc);   // first chunk: exp(-inf)=0
            Z *= sc;
            a0.x *= sc; a0.y *= sc; a0.z *= sc; a0.w *= sc;
            a1.x *= sc; a1.y *= sc; a1.z *= sc; a1.w *= sc;
            m = mc;
        }
        #pragma unroll
        for (int r = 0; r < RCHUNK; r++) {
            const float p = __expf(s[r] - m);
            Z += p;
            a0.x += p * x[r][0].x; a0.y += p * x[r][0].y;
            a0.z += p * x[r][0].z; a0.w += p * x[r][0].w;
            a1.x += p * x[r][1].x; a1.y += p * x[r][1].y;
            a1.z += p * x[r][1].z; a1.w += p * x[r][1].w;
        }
    }

    // intra-CTA combine (4 warps)
    if (lane == 0) { s_wm[w] = m; s_wz[w] = Z; }
    *(float4*)(&s_acc[w][lane * 8])     = a0;
    *(float4*)(&s_acc[w][lane * 8 + 4]) = a1;
    __syncthreads();

    float M = fmaxf(fmaxf(s_wm[0], s_wm[1]), fmaxf(s_wm[2], s_wm[3]));
    float e0 = __expf(s_wm[0] - M), e1 = __expf(s_wm[1] - M);
    float e2 = __expf(s_wm[2] - M), e3 = __expf(s_wm[3] - M);

    if (tid == 0) {
        g_m[cta] = M;
        g_z[cta] = e0 * s_wz[0] + e1 * s_wz[1] + e2 * s_wz[2] + e3 * s_wz[3];
    }
    // each thread combines 2 channels
    #pragma unroll
    for (int jj = 0; jj < 2; jj++) {
        const int j = tid + jj * 128;
        g_acc[(size_t)cta * HH + j] =
            e0 * s_acc[0][j] + e1 * s_acc[1][j] + e2 * s_acc[2][j] + e3 * s_acc[3][j];
    }
}

// ---------------------------------------------------------------------------
// kernel2: merge 16 partials -> ctx; out = tanh(concat(ctx,h_t) @ W_att)
//          grid = BB, 256 thr
// ---------------------------------------------------------------------------
__global__ __launch_bounds__(256)
void k2_combine(const float* __restrict__ hidden,
                const float* __restrict__ Watt,
                float* __restrict__ out)
{
    __shared__ float s_pre[2 * HH];
    __shared__ float s_e[NCHUNK];
    __shared__ float s_Z;

    const int b = blockIdx.x;
    const int tid = threadIdx.x;

    if (tid == 0) {
        float M = -CUDART_INF_F;
        #pragma unroll
        for (int p = 0; p < NCHUNK; p++) M = fmaxf(M, g_m[b * NCHUNK + p]);
        float Zt = 0.f;
        #pragma unroll
        for (int p = 0; p < NCHUNK; p++) {
            const float e = __expf(g_m[b * NCHUNK + p] - M);
            s_e[p] = e;
            Zt += e * g_z[b * NCHUNK + p];
        }
        s_Z = Zt;
    }
    __syncthreads();

    if (tid < HH) {
        float c = 0.f;
        #pragma unroll
        for (int p = 0; p < NCHUNK; p++)
            c += s_e[p] * g_acc[(size_t)(b * NCHUNK + p) * HH + tid];
        s_pre[tid]      = c / s_Z;
        s_pre[HH + tid] = hidden[((size_t)b * TT + (TT - 1)) * HH + tid];
    }
    __syncthreads();

    if (tid < OUTD) {
        float acc = 0.f;
        #pragma unroll 8
        for (int i = 0; i < 2 * HH; i++)
            acc += s_pre[i] * Watt[i * OUTD + tid];
        out[b * OUTD + tid] = tanhf(acc);
    }
}

extern "C" void kernel_launch(void* const* d_in, const int* in_sizes, int n_in,
                              void* d_out, int out_size) {
    const float* hidden = (const float*)d_in[0];   // (128, 2048, 256) f32
    const float* Wscore = (const float*)d_in[1];   // (256, 256) f32
    const float* Watt   = (const float*)d_in[2];   // (512, 128) f32
    float* out = (float*)d_out;                    // (128, 128) f32

    k0_compute_v<<<BB, 128>>>(hidden, Wscore);
    k1_stream<<<BB * NCHUNK, K1_THREADS>>>(hidden);
    k2_combine<<<BB, 256>>>(hidden, Watt, out);
}

// round 3
// speedup vs baseline: 1.2044x; 1.2044x over previous
#include <cuda_runtime.h>
#include <math_constants.h>
#include <cstdint>

#define BB 128
#define TT 2048
#define HH 256
#define OUTD 128

#define NCHUNK 16                        // chunks per batch
#define ROWS_PER_CTA (TT / NCHUNK)       // 128 rows, 128KB
#define NPART (BB * NCHUNK)              // 2048 partials

#define K1_THREADS 256                   // 8 warps
#define K1_WARPS 8
#define TILE_ROWS 8                      // rows per pipeline tile
#define TILE_BYTES (TILE_ROWS * HH * 4)  // 8192
#define NSTAGE 4
#define NTILES (ROWS_PER_CTA / TILE_ROWS) // 16

// Global scratch (allocation-free)
__device__ float g_v[BB * HH];
__device__ float g_m[NPART];
__device__ float g_z[NPART];
__device__ float g_acc[NPART * HH];

// ---------------- PTX helpers ----------------
__device__ __forceinline__ uint32_t s2u(const void* p) {
    uint32_t a;
    asm("{ .reg .u64 t; cvta.to.shared.u64 t, %1; cvt.u32.u64 %0, t; }"
        : "=r"(a) : "l"(p));
    return a;
}
__device__ __forceinline__ void mbar_init(uint32_t bar, uint32_t cnt) {
    asm volatile("mbarrier.init.shared.b64 [%0], %1;" :: "r"(bar), "r"(cnt) : "memory");
}
__device__ __forceinline__ void mbar_expect_tx(uint32_t bar, uint32_t bytes) {
    asm volatile("mbarrier.arrive.expect_tx.shared.b64 _, [%0], %1;"
                 :: "r"(bar), "r"(bytes) : "memory");
}
__device__ __forceinline__ void mbar_arrive(uint32_t bar) {
    asm volatile("mbarrier.arrive.release.cta.shared.b64 _, [%0];" :: "r"(bar) : "memory");
}
__device__ __forceinline__ void mbar_wait(uint32_t bar, uint32_t parity) {
    uint32_t done;
    asm volatile(
        "{ .reg .pred p; mbarrier.try_wait.parity.acquire.cta.shared::cta.b64 p, [%1], %2; "
        "selp.b32 %0, 1, 0, p; }" : "=r"(done) : "r"(bar), "r"(parity) : "memory");
    while (!done) {
        asm volatile(
            "{ .reg .pred p; mbarrier.try_wait.parity.acquire.cta.shared::cta.b64 p, [%1], %2, 0x989680; "
            "selp.b32 %0, 1, 0, p; }" : "=r"(done) : "r"(bar), "r"(parity) : "memory");
    }
}
__device__ __forceinline__ void bulk_copy_g2s(uint32_t dst_smem, const void* src, uint32_t bytes,
                                              uint32_t mbar) {
    asm volatile(
        "cp.async.bulk.shared::cta.global.mbarrier::complete_tx::bytes [%0], [%1], %2, [%3];"
        :: "r"(dst_smem), "l"(src), "r"(bytes), "r"(mbar) : "memory");
}

// ---------------------------------------------------------------------------
// kernel0: v[b,h] = sum_k W_score[h,k] * hidden[b,T-1,k]   grid=BB, 1024 thr
// ---------------------------------------------------------------------------
__global__ __launch_bounds__(1024)
void k0_compute_v(const float* __restrict__ hidden,
                  const float* __restrict__ Wscore)
{
    __shared__ float s_ht[HH];
    const int b = blockIdx.x;
    const int tid = threadIdx.x, w = tid >> 5, lane = tid & 31;
    if (tid < HH) s_ht[tid] = hidden[((size_t)b * TT + (TT - 1)) * HH + tid];
    __syncthreads();

    #pragma unroll
    for (int j = 0; j < 8; j++) {          // warp w -> rows 8w..8w+7
        const int h = w * 8 + j;
        const float* row = Wscore + h * HH;
        float p = 0.f;
        #pragma unroll
        for (int k = lane; k < HH; k += 32) p += row[k] * s_ht[k];
        #pragma unroll
        for (int off = 16; off; off >>= 1) p += __shfl_xor_sync(0xffffffffu, p, off);
        if (lane == 0) g_v[b * HH + h] = p;
    }
}

// ---------------------------------------------------------------------------
// kernel1: bulk-async pipelined streaming online-softmax partials
//          grid = BB*NCHUNK, 256 thr
// ---------------------------------------------------------------------------
__global__ __launch_bounds__(K1_THREADS)
void k1_stream(const float* __restrict__ hidden)
{
    __shared__ __align__(128) float s_tile[NSTAGE][TILE_ROWS * HH];  // 32KB
    __shared__ float s_acc[K1_WARPS][HH];                            // 8KB
    __shared__ float s_wm[K1_WARPS], s_wz[K1_WARPS];
    __shared__ uint64_t s_full[NSTAGE], s_empty[NSTAGE];

    const int cta   = blockIdx.x;
    const int b     = cta >> 4;
    const int chunk = cta & (NCHUNK - 1);
    const int tid   = threadIdx.x, w = tid >> 5, lane = tid & 31;

    const uint32_t full0  = s2u(&s_full[0]);
    const uint32_t empty0 = s2u(&s_empty[0]);
    const uint32_t tile0  = s2u(&s_tile[0][0]);

    const float* src = hidden + ((size_t)b * TT + chunk * ROWS_PER_CTA) * HH;

    if (tid == 0) {
        #pragma unroll
        for (int s = 0; s < NSTAGE; s++) {
            mbar_init(full0 + s * 8, 1);
            mbar_init(empty0 + s * 8, K1_WARPS);
        }
    }
    __syncthreads();

    // prologue: fill all stages
    if (tid == 0) {
        #pragma unroll
        for (int s = 0; s < NSTAGE; s++) {
            mbar_expect_tx(full0 + s * 8, TILE_BYTES);
            bulk_copy_g2s(tile0 + s * TILE_BYTES, src + s * TILE_ROWS * HH,
                          TILE_BYTES, full0 + s * 8);
        }
    }

    // per-lane v slice: channels [4*lane .. 4*lane+3] and [128+4*lane .. +3]
    const float4 v0 = *(const float4*)(g_v + b * HH + lane * 4);
    const float4 v1 = *(const float4*)(g_v + b * HH + 128 + lane * 4);

    float  m = -CUDART_INF_F, Z = 0.f;
    float4 a0 = make_float4(0.f, 0.f, 0.f, 0.f);
    float4 a1 = make_float4(0.f, 0.f, 0.f, 0.f);

    for (int i = 0; i < NTILES; i++) {
        const int s  = i & (NSTAGE - 1);
        const uint32_t ph = (i >> 2) & 1;
        mbar_wait(full0 + s * 8, ph);

        // warp w processes row w of this tile (1KB in smem)
        const float* row = &s_tile[s][w * HH];
        const float4 x0 = *(const float4*)(row + lane * 4);
        const float4 x1 = *(const float4*)(row + 128 + lane * 4);

        float sc = x0.x * v0.x + x0.y * v0.y + x0.z * v0.z + x0.w * v0.w
                 + x1.x * v1.x + x1.y * v1.y + x1.z * v1.z + x1.w * v1.w;
        #pragma unroll
        for (int off = 16; off; off >>= 1) sc += __shfl_xor_sync(0xffffffffu, sc, off);

        if (sc > m) {                       // warp-uniform
            const float r = __expf(m - sc); // first tile: exp(-inf)=0
            Z *= r;
            a0.x *= r; a0.y *= r; a0.z *= r; a0.w *= r;
            a1.x *= r; a1.y *= r; a1.z *= r; a1.w *= r;
            m = sc;
        }
        const float p = __expf(sc - m);
        Z += p;
        a0.x += p * x0.x; a0.y += p * x0.y; a0.z += p * x0.z; a0.w += p * x0.w;
        a1.x += p * x1.x; a1.y += p * x1.y; a1.z += p * x1.z; a1.w += p * x1.w;

        if (lane == 0) mbar_arrive(empty0 + s * 8);

        // producer refills this stage with tile i+NSTAGE
        if (tid == 0 && i + NSTAGE < NTILES) {
            mbar_wait(empty0 + s * 8, ph);  // all 8 warps done with stage s
            mbar_expect_tx(full0 + s * 8, TILE_BYTES);
            bulk_copy_g2s(tile0 + s * TILE_BYTES,
                          src + (size_t)(i + NSTAGE) * TILE_ROWS * HH,
                          TILE_BYTES, full0 + s * 8);
        }
    }

    // intra-CTA combine (8 warps)
    if (lane == 0) { s_wm[w] = m; s_wz[w] = Z; }
    *(float4*)(&s_acc[w][lane * 4])       = a0;
    *(float4*)(&s_acc[w][128 + lane * 4]) = a1;
    __syncthreads();

    float M = -CUDART_INF_F;
    #pragma unroll
    for (int ww = 0; ww < K1_WARPS; ww++) M = fmaxf(M, s_wm[ww]);
    float e[K1_WARPS], Zt = 0.f;
    #pragma unroll
    for (int ww = 0; ww < K1_WARPS; ww++) {
        e[ww] = __expf(s_wm[ww] - M);
        Zt += e[ww] * s_wz[ww];
    }
    if (tid == 0) { g_m[cta] = M; g_z[cta] = Zt; }
    {
        float c = 0.f;
        #pragma unroll
        for (int ww = 0; ww < K1_WARPS; ww++) c += e[ww] * s_acc[ww][tid];
        g_acc[(size_t)cta * HH + tid] = c;
    }
}

// ---------------------------------------------------------------------------
// kernel2: merge partials -> ctx; out = tanh(concat(ctx,h_t) @ W_att)
//          grid = BB, 256 thr
// ---------------------------------------------------------------------------
__global__ __launch_bounds__(256)
void k2_combine(const float* __restrict__ hidden,
                const float* __restrict__ Watt,
                float* __restrict__ out)
{
    __shared__ float s_pre[2 * HH];
    __shared__ float s_e[NCHUNK];
    __shared__ float s_Z;

    const int b = blockIdx.x;
    const int tid = threadIdx.x, lane = tid & 31;

    if (tid < 32) {
        float mv = (lane < NCHUNK) ? g_m[b * NCHUNK + lane] : -CUDART_INF_F;
        float M = mv;
        #pragma unroll
        for (int off = 16; off; off >>= 1) M = fmaxf(M, __shfl_xor_sync(0xffffffffu, M, off));
        float ev = (lane < NCHUNK) ? __expf(mv - M) : 0.f;
        float zv = (lane < NCHUNK) ? ev * g_z[b * NCHUNK + lane] : 0.f;
        #pragma unroll
        for (int off = 16; off; off >>= 1) zv += __shfl_xor_sync(0xffffffffu, zv, off);
        if (lane < NCHUNK) s_e[lane] = ev;
        if (lane == 0) s_Z = zv;
    }
    __syncthreads();

    if (tid < HH) {
        float c = 0.f;
        #pragma unroll
        for (int p = 0; p < NCHUNK; p++)
            c += s_e[p] * g_acc[(size_t)(b * NCHUNK + p) * HH + tid];
        s_pre[tid]      = c / s_Z;
        s_pre[HH + tid] = hidden[((size_t)b * TT + (TT - 1)) * HH + tid];
    }
    __syncthreads();

    if (tid < OUTD) {
        float acc = 0.f;
        #pragma unroll 8
        for (int i = 0; i < 2 * HH; i++)
            acc += s_pre[i] * Watt[i * OUTD + tid];
        out[b * OUTD + tid] = tanhf(acc);
    }
}

extern "C" void kernel_launch(void* const* d_in, const int* in_sizes, int n_in,
                              void* d_out, int out_size) {
    const float* hidden = (const float*)d_in[0];   // (128, 2048, 256) f32
    const float* Wscore = (const float*)d_in[1];   // (256, 256) f32
    const float* Watt   = (const float*)d_in[2];   // (512, 128) f32
    float* out = (float*)d_out;                    // (128, 128) f32

    k0_compute_v<<<BB, 1024>>>(hidden, Wscore);
    k1_stream<<<BB * NCHUNK, K1_THREADS>>>(hidden);
    k2_combine<<<BB, 256>>>(hidden, Watt, out);
}

// round 5
// speedup vs baseline: 1.3401x; 1.1127x over previous
#include <cuda_runtime.h>
#include <math_constants.h>
#include <cstdint>

#define BB 128
#define TT 2048
#define HH 256
#define OUTD 128

#define NCHUNK 8                          // chunks per batch
#define ROWS_PER_CTA (TT / NCHUNK)        // 256 rows
#define NPART (BB * NCHUNK)               // 1024

#define K1_THREADS 128                    // 4 warps
#define K1_WARPS 4
#define ROWS_PER_WARP (ROWS_PER_CTA / K1_WARPS)   // 64
#define STAGE_ROWS 4
#define STAGE_BYTES (STAGE_ROWS * HH * 4) // 4096
#define NSTAGE 4
#define ITERS (ROWS_PER_WARP / STAGE_ROWS) // 16

// dynamic smem layout (bytes)
#define OFF_TILES 0
#define SZ_TILES  (K1_WARPS * NSTAGE * STAGE_BYTES)    // 65536
#define OFF_ACC   (OFF_TILES + SZ_TILES)               // 65536
#define SZ_ACC    (K1_WARPS * HH * 4)                  // 4096
#define OFF_WM    (OFF_ACC + SZ_ACC)                   // 69632
#define OFF_WZ    (OFF_WM + 16)
#define OFF_BARS  (OFF_WZ + 16)                        // 69664 (8-aligned)
#define SMEM_K1   (OFF_BARS + K1_WARPS * NSTAGE * 8)   // 69792

// Global scratch (allocation-free)
__device__ float g_v[BB * HH];
__device__ float g_m[NPART];
__device__ float g_z[NPART];
__device__ float g_acc[NPART * HH];

// ---------------- PTX helpers ----------------
__device__ __forceinline__ uint32_t s2u(const void* p) {
    uint32_t a;
    asm("{ .reg .u64 t; cvta.to.shared.u64 t, %1; cvt.u32.u64 %0, t; }"
        : "=r"(a) : "l"(p));
    return a;
}
__device__ __forceinline__ void mbar_init(uint32_t bar, uint32_t cnt) {
    asm volatile("mbarrier.init.shared.b64 [%0], %1;" :: "r"(bar), "r"(cnt) : "memory");
}
__device__ __forceinline__ void mbar_expect_tx(uint32_t bar, uint32_t bytes) {
    asm volatile("mbarrier.arrive.expect_tx.shared.b64 _, [%0], %1;"
                 :: "r"(bar), "r"(bytes) : "memory");
}
__device__ __forceinline__ void mbar_wait(uint32_t bar, uint32_t parity) {
    uint32_t done;
    asm volatile(
        "{ .reg .pred p; mbarrier.try_wait.parity.acquire.cta.shared::cta.b64 p, [%1], %2; "
        "selp.b32 %0, 1, 0, p; }" : "=r"(done) : "r"(bar), "r"(parity) : "memory");
    while (!done) {
        asm volatile(
            "{ .reg .pred p; mbarrier.try_wait.parity.acquire.cta.shared::cta.b64 p, [%1], %2, 0x989680; "
            "selp.b32 %0, 1, 0, p; }" : "=r"(done) : "r"(bar), "r"(parity) : "memory");
    }
}
__device__ __forceinline__ void bulk_copy_g2s(uint32_t dst_smem, const void* src,
                                              uint32_t bytes, uint32_t mbar) {
    asm volatile(
        "cp.async.bulk.shared::cta.global.mbarrier::complete_tx::bytes [%0], [%1], %2, [%3];"
        :: "r"(dst_smem), "l"(src), "r"(bytes), "r"(mbar) : "memory");
}
__device__ __forceinline__ void fence_async_shared() {
    asm volatile("fence.proxy.async.shared::cta;" ::: "memory");
}

// ---------------------------------------------------------------------------
// kernel0: V[b,h] = sum_k W_score[h,k]*ht[b,k].  grid=64, each CTA: 4 h-rows,
//          all 128 batches.  W_score read ~once total (256KB, not 32MB).
// ---------------------------------------------------------------------------
__global__ __launch_bounds__(256)
void k0_compute_v(const float* __restrict__ hidden,
                  const float* __restrict__ Wscore)
{
    __shared__ float sW[4 * HH];
    const int hbase = blockIdx.x * 4;
    const int tid = threadIdx.x, ww = tid >> 5, lane = tid & 31;

    #pragma unroll
    for (int k = 0; k < 4; k++) sW[tid + k * 256] = Wscore[hbase * HH + tid + k * 256];
    __syncthreads();

    // W rows in registers (channels lane*4.. and 128+lane*4..)
    float4 w0[4], w1[4];
    #pragma unroll
    for (int r = 0; r < 4; r++) {
        w0[r] = *(const float4*)(sW + r * HH + lane * 4);
        w1[r] = *(const float4*)(sW + r * HH + 128 + lane * 4);
    }

    // warp ww handles batches ww, ww+8, ..., 16 batches; prefetch ht
    const float* htb = hidden + ((size_t)ww * TT + (TT - 1)) * HH;
    float4 h0 = *(const float4*)(htb + lane * 4);
    float4 h1 = *(const float4*)(htb + 128 + lane * 4);

    for (int k = 0; k < 16; k++) {
        const int b = ww + 8 * k;
        float4 n0, n1;
        if (k < 15) {
            const float* nb = hidden + ((size_t)(b + 8) * TT + (TT - 1)) * HH;
            n0 = *(const float4*)(nb + lane * 4);
            n1 = *(const float4*)(nb + 128 + lane * 4);
        }
        float s[4];
        #pragma unroll
        for (int r = 0; r < 4; r++) {
            s[r] = h0.x * w0[r].x + h0.y * w0[r].y + h0.z * w0[r].z + h0.w * w0[r].w
                 + h1.x * w1[r].x + h1.y * w1[r].y + h1.z * w1[r].z + h1.w * w1[r].w;
        }
        #pragma unroll
        for (int off = 16; off; off >>= 1) {
            #pragma unroll
            for (int r = 0; r < 4; r++) s[r] += __shfl_xor_sync(0xffffffffu, s[r], off);
        }
        const float val = (lane == 0) ? s[0] : (lane == 1) ? s[1]
                        : (lane == 2) ? s[2] : s[3];
        if (lane < 4) g_v[b * HH + hbase + lane] = val;
        h0 = n0; h1 = n1;
    }
}

// ---------------------------------------------------------------------------
// kernel1: per-warp self-paced bulk-async pipeline, online softmax partials.
//          grid = BB*NCHUNK = 1024, 128 thr, ~70KB dyn smem -> 3 CTAs/SM.
// ---------------------------------------------------------------------------
__global__ __launch_bounds__(K1_THREADS, 3)
void k1_stream(const float* __restrict__ hidden)
{
    extern __shared__ __align__(128) unsigned char smem_raw[];
    float* s_tiles = (float*)(smem_raw + OFF_TILES);
    float* s_acc   = (float*)(smem_raw + OFF_ACC);
    float* s_wm    = (float*)(smem_raw + OFF_WM);
    float* s_wz    = (float*)(smem_raw + OFF_WZ);

    const int cta   = blockIdx.x;
    const int b     = cta >> 3;               // / NCHUNK
    const int chunk = cta & (NCHUNK - 1);
    const int tid   = threadIdx.x, w = tid >> 5, lane = tid & 31;

    const uint32_t bar0  = s2u(smem_raw + OFF_BARS) + w * NSTAGE * 8;
    const uint32_t tile0 = s2u(smem_raw) + w * NSTAGE * STAGE_BYTES;
    float* tbase = s_tiles + w * NSTAGE * (STAGE_ROWS * HH);

    const float* src = hidden
        + ((size_t)b * TT + chunk * ROWS_PER_CTA + w * ROWS_PER_WARP) * HH;

    // per-warp barrier init + prologue copies (no cross-warp sync needed)
    if (lane == 0) {
        #pragma unroll
        for (int s = 0; s < NSTAGE; s++) mbar_init(bar0 + s * 8, 1);
        fence_async_shared();
        #pragma unroll
        for (int s = 0; s < NSTAGE; s++) {
            mbar_expect_tx(bar0 + s * 8, STAGE_BYTES);
            bulk_copy_g2s(tile0 + s * STAGE_BYTES,
                          src + (size_t)s * STAGE_ROWS * HH,
                          STAGE_BYTES, bar0 + s * 8);
        }
    }
    __syncwarp();

    // per-lane v slice (channels lane*4.. and 128+lane*4..)
    const float4 v0 = *(const float4*)(g_v + b * HH + lane * 4);
    const float4 v1 = *(const float4*)(g_v + b * HH + 128 + lane * 4);

    float  m = -CUDART_INF_F, Z = 0.f;
    float4 a0 = make_float4(0.f, 0.f, 0.f, 0.f);
    float4 a1 = make_float4(0.f, 0.f, 0.f, 0.f);

    for (int i = 0; i < ITERS; i++) {
        const int s = i & (NSTAGE - 1);
        mbar_wait(bar0 + s * 8, (i >> 2) & 1);

        const float* tp = tbase + s * (STAGE_ROWS * HH);
        float4 x[STAGE_ROWS][2];
        #pragma unroll
        for (int r = 0; r < STAGE_ROWS; r++) {
            x[r][0] = *(const float4*)(tp + r * HH + lane * 4);
            x[r][1] = *(const float4*)(tp + r * HH + 128 + lane * 4);
        }

        // consume the registers first (score FMAs)...
        float sc[STAGE_ROWS];
        #pragma unroll
        for (int r = 0; r < STAGE_ROWS; r++) {
            sc[r] = x[r][0].x * v0.x + x[r][0].y * v0.y + x[r][0].z * v0.z + x[r][0].w * v0.w
                  + x[r][1].x * v1.x + x[r][1].y * v1.y + x[r][1].z * v1.z + x[r][1].w * v1.w;
        }

        // ...then refill stage s. __syncwarp guarantees every lane's LDS of
        // this stage has issued/completed before lane 0 overwrites it.
        __syncwarp();
        if (lane == 0 && i + NSTAGE < ITERS) {
            mbar_expect_tx(bar0 + s * 8, STAGE_BYTES);
            bulk_copy_g2s(tile0 + s * STAGE_BYTES,
                          src + (size_t)(i + NSTAGE) * STAGE_ROWS * HH,
                          STAGE_BYTES, bar0 + s * 8);
        }

        #pragma unroll
        for (int off = 16; off; off >>= 1) {
            #pragma unroll
            for (int r = 0; r < STAGE_ROWS; r++)
                sc[r] += __shfl_xor_sync(0xffffffffu, sc[r], off);
        }
        const float mc = fmaxf(fmaxf(sc[0], sc[1]), fmaxf(sc[2], sc[3]));
        if (mc > m) {                          // warp-uniform
            const float rr = __expf(m - mc);   // first stage: exp(-inf)=0
            Z *= rr;
            a0.x *= rr; a0.y *= rr; a0.z *= rr; a0.w *= rr;
            a1.x *= rr; a1.y *= rr; a1.z *= rr; a1.w *= rr;
            m = mc;
        }
        #pragma unroll
        for (int r = 0; r < STAGE_ROWS; r++) {
            const float p = __expf(sc[r] - m);
            Z += p;
            a0.x += p * x[r][0].x; a0.y += p * x[r][0].y;
            a0.z += p * x[r][0].z; a0.w += p * x[r][0].w;
            a1.x += p * x[r][1].x; a1.y += p * x[r][1].y;
            a1.z += p * x[r][1].z; a1.w += p * x[r][1].w;
        }
    }

    // intra-CTA combine (4 warps)
    if (lane == 0) { s_wm[w] = m; s_wz[w] = Z; }
    *(float4*)(&s_acc[w * HH + lane * 4])       = a0;
    *(float4*)(&s_acc[w * HH + 128 + lane * 4]) = a1;
    __syncthreads();

    const float M = fmaxf(fmaxf(s_wm[0], s_wm[1]), fmaxf(s_wm[2], s_wm[3]));
    const float e0 = __expf(s_wm[0] - M), e1 = __expf(s_wm[1] - M);
    const float e2 = __expf(s_wm[2] - M), e3 = __expf(s_wm[3] - M);

    if (tid == 0) {
        g_m[cta] = M;
        g_z[cta] = e0 * s_wz[0] + e1 * s_wz[1] + e2 * s_wz[2] + e3 * s_wz[3];
    }
    #pragma unroll
    for (int jj = 0; jj < 2; jj++) {
        const int ch = tid + jj * 128;
        g_acc[(size_t)cta * HH + ch] =
            e0 * s_acc[0 * HH + ch] + e1 * s_acc[1 * HH + ch]
          + e2 * s_acc[2 * HH + ch] + e3 * s_acc[3 * HH + ch];
    }
}

// ---------------------------------------------------------------------------
// kernel2: merge partials -> ctx; out = tanh(concat(ctx,h_t) @ W_att).
//          grid = 16 CTAs x 8 batches, 512 thr, W_att staged through smem.
// ---------------------------------------------------------------------------
__global__ __launch_bounds__(512)
void k2_combine(const float* __restrict__ hidden,
                const float* __restrict__ Watt,
                float* __restrict__ out)
{
    __shared__ float s_pre[8][2 * HH];   // 16KB
    __shared__ float s_e[8][NCHUNK];
    __shared__ float s_Z[8];
    __shared__ float sW[32 * OUTD];      // 16KB W_att tile

    const int b0 = blockIdx.x * 8;
    const int tid = threadIdx.x;

    if (tid < 8 * NCHUNK) {              // stash m values
        const int bi = tid >> 3, p = tid & 7;
        s_e[bi][p] = g_m[(b0 + bi) * NCHUNK + p];
    }
    __syncthreads();
    if (tid < 8) {
        float M = -CUDART_INF_F;
        #pragma unroll
        for (int p = 0; p < NCHUNK; p++) M = fmaxf(M, s_e[tid][p]);
        float Zt = 0.f;
        #pragma unroll
        for (int p = 0; p < NCHUNK; p++) {
            const float e = __expf(s_e[tid][p] - M);
            Zt += e * g_z[(b0 + tid) * NCHUNK + p];
            s_e[tid][p] = e;
        }
        s_Z[tid] = Zt;
    }
    __syncthreads();

    const int bi = tid >> 6, c0 = tid & 63;
    #pragma unroll
    for (int cc = 0; cc < 4; cc++) {
        const int ch = c0 + cc * 64;
        float c = 0.f;
        #pragma unroll
        for (int p = 0; p < NCHUNK; p++)
            c += s_e[bi][p] * g_acc[(size_t)((b0 + bi) * NCHUNK + p) * HH + ch];
        s_pre[bi][ch]      = c / s_Z[bi];
        s_pre[bi][HH + ch] = hidden[((size_t)(b0 + bi) * TT + (TT - 1)) * HH + ch];
    }
    __syncthreads();

    // out[bi][j], 2 outputs per thread; W_att tiled 32 rows at a time via smem
    const int j = tid & 63;
    float acc0 = 0.f, acc1 = 0.f;
    for (int t = 0; t < 16; t++) {
        #pragma unroll
        for (int q = 0; q < 8; q++)      // 512 thr load 32x128 = 4096 floats
            sW[tid + q * 512] = Watt[(t * 32) * OUTD + tid + q * 512];
        __syncthreads();
        #pragma unroll
        for (int i = 0; i < 32; i++) {
            const float p = s_pre[bi][t * 32 + i];
            acc0 += p * sW[i * OUTD + j];
            acc1 += p * sW[i * OUTD + j + 64];
        }
        __syncthreads();
    }
    out[(b0 + bi) * OUTD + j]      = tanhf(acc0);
    out[(b0 + bi) * OUTD + j + 64] = tanhf(acc1);
}

extern "C" void kernel_launch(void* const* d_in, const int* in_sizes, int n_in,
                              void* d_out, int out_size) {
    const float* hidden = (const float*)d_in[0];   // (128, 2048, 256) f32
    const float* Wscore = (const float*)d_in[1];   // (256, 256) f32
    const float* Watt   = (const float*)d_in[2];   // (512, 128) f32
    float* out = (float*)d_out;                    // (128, 128) f32

    cudaFuncSetAttribute(k1_stream, cudaFuncAttributeMaxDynamicSharedMemorySize, SMEM_K1);

    k0_compute_v<<<64, 256>>>(hidden, Wscore);
    k1_stream<<<BB * NCHUNK, K1_THREADS, SMEM_K1>>>(hidden);
    k2_combine<<<16, 512>>>(hidden, Watt, out);
}

// round 7
// speedup vs baseline: 1.3977x; 1.0429x over previous
#include <cuda_runtime.h>
#include <math_constants.h>
#include <cstdint>

#define BB 128
#define TT 2048
#define HH 256
#define OUTD 128

#define NCHUNK 8                          // chunks per batch
#define ROWS_PER_CTA (TT / NCHUNK)        // 256 rows
#define NPART (BB * NCHUNK)               // 1024

#define K1_THREADS 128                    // 4 warps
#define K1_WARPS 4
#define ROWS_PER_WARP (ROWS_PER_CTA / K1_WARPS)   // 64
#define STAGE_ROWS 4
#define STAGE_BYTES (STAGE_ROWS * HH * 4) // 4096
#define NSTAGE 3
#define ITERS (ROWS_PER_WARP / STAGE_ROWS) // 16

// dynamic smem layout (bytes)
#define OFF_TILES 0
#define SZ_TILES  (K1_WARPS * NSTAGE * STAGE_BYTES)    // 49152
#define OFF_ACC   (OFF_TILES + SZ_TILES)
#define SZ_ACC    (K1_WARPS * HH * 4)                  // 4096
#define OFF_WM    (OFF_ACC + SZ_ACC)
#define OFF_WZ    (OFF_WM + 16)
#define OFF_BARS  (OFF_WZ + 16)                        // 8-aligned
#define SMEM_K1   (OFF_BARS + K1_WARPS * NSTAGE * 8)   // 53376 -> 4 CTAs/SM

// Global scratch (allocation-free)
__device__ float g_v[BB * HH];
__device__ float g_m[NPART];
__device__ float g_z[NPART];
__device__ float g_acc[NPART * HH];

// ---------------- PTX helpers ----------------
__device__ __forceinline__ uint32_t s2u(const void* p) {
    uint32_t a;
    asm("{ .reg .u64 t; cvta.to.shared.u64 t, %1; cvt.u32.u64 %0, t; }"
        : "=r"(a) : "l"(p));
    return a;
}
__device__ __forceinline__ void mbar_init(uint32_t bar, uint32_t cnt) {
    asm volatile("mbarrier.init.shared.b64 [%0], %1;" :: "r"(bar), "r"(cnt) : "memory");
}
__device__ __forceinline__ void mbar_expect_tx(uint32_t bar, uint32_t bytes) {
    asm volatile("mbarrier.arrive.expect_tx.shared.b64 _, [%0], %1;"
                 :: "r"(bar), "r"(bytes) : "memory");
}
__device__ __forceinline__ void mbar_wait(uint32_t bar, uint32_t parity) {
    uint32_t done;
    asm volatile(
        "{ .reg .pred p; mbarrier.try_wait.parity.acquire.cta.shared::cta.b64 p, [%1], %2; "
        "selp.b32 %0, 1, 0, p; }" : "=r"(done) : "r"(bar), "r"(parity) : "memory");
    while (!done) {
        asm volatile(
            "{ .reg .pred p; mbarrier.try_wait.parity.acquire.cta.shared::cta.b64 p, [%1], %2, 0x989680; "
            "selp.b32 %0, 1, 0, p; }" : "=r"(done) : "r"(bar), "r"(parity) : "memory");
    }
}
__device__ __forceinline__ void bulk_copy_g2s(uint32_t dst_smem, const void* src,
                                              uint32_t bytes, uint32_t mbar) {
    asm volatile(
        "cp.async.bulk.shared::cta.global.mbarrier::complete_tx::bytes [%0], [%1], %2, [%3];"
        :: "r"(dst_smem), "l"(src), "r"(bytes), "r"(mbar) : "memory");
}
__device__ __forceinline__ void fence_async_shared() {
    asm volatile("fence.proxy.async.shared::cta;" ::: "memory");
}

// ---------------------------------------------------------------------------
// kernel0: V[b,h] = sum_k W_score[h,k]*ht[b,k]  as a tiled mini-GEMM.
//          grid = (8 b-tiles, 16 h-tiles) = 128 CTAs, 256 thr, 1 output/thr.
// ---------------------------------------------------------------------------
#define K0_BT 16
#define K0_HT 16
#define K0_PAD 260          // 16B-aligned row pad, conflict-free phases

__global__ __launch_bounds__(256)
void k0_compute_v(const float* __restrict__ hidden,
                  const float* __restrict__ Wscore)
{
    __shared__ float sW [K0_HT][K0_PAD];
    __shared__ float sHt[K0_BT][K0_PAD];

    const int b0 = blockIdx.x * K0_BT;
    const int h0 = blockIdx.y * K0_HT;
    const int tid = threadIdx.x;

    // cooperative tile loads: row = tid>>4, 16-float segment = tid&15
    {
        const int row = tid >> 4, q = (tid & 15) * 16;
        const float* wsrc = Wscore + (size_t)(h0 + row) * HH + q;
        const float* hsrc = hidden + ((size_t)(b0 + row) * TT + (TT - 1)) * HH + q;
        #pragma unroll
        for (int u = 0; u < 4; u++) {
            *(float4*)&sW [row][q + u * 4] = *(const float4*)(wsrc + u * 4);
            *(float4*)&sHt[row][q + u * 4] = *(const float4*)(hsrc + u * 4);
        }
    }
    __syncthreads();

    // thread (h = tid>>4, b = tid&15): dot of length 256 from smem
    const int h = tid >> 4, b = tid & 15;
    float acc = 0.f;
    #pragma unroll 8
    for (int k = 0; k < HH; k += 4) {
        const float4 wv = *(const float4*)&sW[h][k];
        const float4 hv = *(const float4*)&sHt[b][k];
        acc += wv.x * hv.x + wv.y * hv.y + wv.z * hv.z + wv.w * hv.w;
    }
    g_v[(b0 + b) * HH + h0 + h] = acc;
}

// ---------------------------------------------------------------------------
// kernel1: per-warp self-paced bulk-async pipeline, online softmax partials.
//          grid = BB*NCHUNK = 1024, 128 thr, ~52KB dyn smem -> 4 CTAs/SM.
// ---------------------------------------------------------------------------
__global__ __launch_bounds__(K1_THREADS, 4)
void k1_stream(const float* __restrict__ hidden)
{
    extern __shared__ __align__(128) unsigned char smem_raw[];
    float* s_tiles = (float*)(smem_raw + OFF_TILES);
    float* s_acc   = (float*)(smem_raw + OFF_ACC);
    float* s_wm    = (float*)(smem_raw + OFF_WM);
    float* s_wz    = (float*)(smem_raw + OFF_WZ);

    const int cta   = blockIdx.x;
    const int b     = cta >> 3;               // / NCHUNK
    const int chunk = cta & (NCHUNK - 1);
    const int tid   = threadIdx.x, w = tid >> 5, lane = tid & 31;

    const uint32_t bar0  = s2u(smem_raw + OFF_BARS) + w * NSTAGE * 8;
    const uint32_t tile0 = s2u(smem_raw) + w * NSTAGE * STAGE_BYTES;
    float* tbase = s_tiles + w * NSTAGE * (STAGE_ROWS * HH);

    const float* src = hidden
        + ((size_t)b * TT + chunk * ROWS_PER_CTA + w * ROWS_PER_WARP) * HH;

    // per-warp barrier init + prologue copies (no cross-warp sync needed)
    if (lane == 0) {
        #pragma unroll
        for (int s = 0; s < NSTAGE; s++) mbar_init(bar0 + s * 8, 1);
        fence_async_shared();
        #pragma unroll
        for (int s = 0; s < NSTAGE; s++) {
            mbar_expect_tx(bar0 + s * 8, STAGE_BYTES);
            bulk_copy_g2s(tile0 + s * STAGE_BYTES,
                          src + (size_t)s * STAGE_ROWS * HH,
                          STAGE_BYTES, bar0 + s * 8);
        }
    }
    __syncwarp();

    // per-lane v slice (channels lane*4.. and 128+lane*4..)
    const float4 v0 = *(const float4*)(g_v + b * HH + lane * 4);
    const float4 v1 = *(const float4*)(g_v + b * HH + 128 + lane * 4);

    float  m = -CUDART_INF_F, Z = 0.f;
    float4 a0 = make_float4(0.f, 0.f, 0.f, 0.f);
    float4 a1 = make_float4(0.f, 0.f, 0.f, 0.f);

    int s = 0, ph = 0;                        // incremental stage/parity
    for (int i = 0; i < ITERS; i++) {
        mbar_wait(bar0 + s * 8, ph);

        const float* tp = tbase + s * (STAGE_ROWS * HH);
        float4 x[STAGE_ROWS][2];
        #pragma unroll
        for (int r = 0; r < STAGE_ROWS; r++) {
            x[r][0] = *(const float4*)(tp + r * HH + lane * 4);
            x[r][1] = *(const float4*)(tp + r * HH + 128 + lane * 4);
        }

        // consume the registers first (score FMAs)...
        float sc[STAGE_ROWS];
        #pragma unroll
        for (int r = 0; r < STAGE_ROWS; r++) {
            sc[r] = x[r][0].x * v0.x + x[r][0].y * v0.y + x[r][0].z * v0.z + x[r][0].w * v0.w
                  + x[r][1].x * v1.x + x[r][1].y * v1.y + x[r][1].z * v1.z + x[r][1].w * v1.w;
        }

        // ...then refill stage s (all lanes' LDS done per __syncwarp)
        __syncwarp();
        if (lane == 0 && i + NSTAGE < ITERS) {
            mbar_expect_tx(bar0 + s * 8, STAGE_BYTES);
            bulk_copy_g2s(tile0 + s * STAGE_BYTES,
                          src + (size_t)(i + NSTAGE) * STAGE_ROWS * HH,
                          STAGE_BYTES, bar0 + s * 8);
        }

        #pragma unroll
        for (int off = 16; off; off >>= 1) {
            #pragma unroll
            for (int r = 0; r < STAGE_ROWS; r++)
                sc[r] += __shfl_xor_sync(0xffffffffu, sc[r], off);
        }
        const float mc = fmaxf(fmaxf(sc[0], sc[1]), fmaxf(sc[2], sc[3]));
        if (mc > m) {                          // warp-uniform
            const float rr = __expf(m - mc);   // first stage: exp(-inf)=0
            Z *= rr;
            a0.x *= rr; a0.y *= rr; a0.z *= rr; a0.w *= rr;
            a1.x *= rr; a1.y *= rr; a1.z *= rr; a1.w *= rr;
            m = mc;
        }
        #pragma unroll
        for (int r = 0; r < STAGE_ROWS; r++) {
            const float p = __expf(sc[r] - m);
            Z += p;
            a0.x += p * x[r][0].x; a0.y += p * x[r][0].y;
            a0.z += p * x[r][0].z; a0.w += p * x[r][0].w;
            a1.x += p * x[r][1].x; a1.y += p * x[r][1].y;
            a1.z += p * x[r][1].z; a1.w += p * x[r][1].w;
        }

        if (++s == NSTAGE) { s = 0; ph ^= 1; }
    }

    // intra-CTA combine (4 warps)
    if (lane == 0) { s_wm[w] = m; s_wz[w] = Z; }
    *(float4*)(&s_acc[w * HH + lane * 4])       = a0;
    *(float4*)(&s_acc[w * HH + 128 + lane * 4]) = a1;
    __syncthreads();

    const float M = fmaxf(fmaxf(s_wm[0], s_wm[1]), fmaxf(s_wm[2], s_wm[3]));
    const float e0 = __expf(s_wm[0] - M), e1 = __expf(s_wm[1] - M);
    const float e2 = __expf(s_wm[2] - M), e3 = __expf(s_wm[3] - M);

    if (tid == 0) {
        g_m[cta] = M;
        g_z[cta] = e0 * s_wz[0] + e1 * s_wz[1] + e2 * s_wz[2] + e3 * s_wz[3];
    }
    #pragma unroll
    for (int jj = 0; jj < 2; jj++) {
        const int ch = tid + jj * 128;
        g_acc[(size_t)cta * HH + ch] =
            e0 * s_acc[0 * HH + ch] + e1 * s_acc[1 * HH + ch]
          + e2 * s_acc[2 * HH + ch] + e3 * s_acc[3 * HH + ch];
    }
}

// ---------------------------------------------------------------------------
// kernel2: merge partials -> ctx; out = tanh(concat(ctx,h_t) @ W_att).
//          grid = 16 CTAs x 8 batches, 512 thr, W_att staged through smem.
// ---------------------------------------------------------------------------
__global__ __launch_bounds__(512)
void k2_combine(const float* __restrict__ hidden,
                const float* __restrict__ Watt,
                float* __restrict__ out)
{
    __shared__ float s_pre[8][2 * HH];   // 16KB
    __shared__ float s_e[8][NCHUNK];
    __shared__ float s_Z[8];
    __shared__ float sW[32 * OUTD];      // 16KB W_att tile

    const int b0 = blockIdx.x * 8;
    const int tid = threadIdx.x;

    if (tid < 8 * NCHUNK) {              // stash m values
        const int bi = tid >> 3, p = tid & 7;
        s_e[bi][p] = g_m[(b0 + bi) * NCHUNK + p];
    }
    __syncthreads();
    if (tid < 8) {
        float M = -CUDART_INF_F;
        #pragma unroll
        for (int p = 0; p < NCHUNK; p++) M = fmaxf(M, s_e[tid][p]);
        float Zt = 0.f;
        #pragma unroll
        for (int p = 0; p < NCHUNK; p++) {
            const float e = __expf(s_e[tid][p] - M);
            Zt += e * g_z[(b0 + tid) * NCHUNK + p];
            s_e[tid][p] = e;
        }
        s_Z[tid] = Zt;
    }
    __syncthreads();

    const int bi = tid >> 6, c0 = tid & 63;
    #pragma unroll
    for (int cc = 0; cc < 4; cc++) {
        const int ch = c0 + cc * 64;
        float c = 0.f;
        #pragma unroll
        for (int p = 0; p < NCHUNK; p++)
            c += s_e[bi][p] * g_acc[(size_t)((b0 + bi) * NCHUNK + p) * HH + ch];
        s_pre[bi][ch]      = c / s_Z[bi];
        s_pre[bi][HH + ch] = hidden[((size_t)(b0 + bi) * TT + (TT - 1)) * HH + ch];
    }
    __syncthreads();

    // out[bi][j], 2 outputs per thread; W_att tiled 32 rows at a time via smem
    const int j = tid & 63;
    float acc0 = 0.f, acc1 = 0.f;
    for (int t = 0; t < 16; t++) {
        #pragma unroll
        for (int q = 0; q < 8; q++)      // 512 thr load 32x128 = 4096 floats
            sW[tid + q * 512] = Watt[(t * 32) * OUTD + tid + q * 512];
        __syncthreads();
        #pragma unroll
        for (int i = 0; i < 32; i++) {
            const float p = s_pre[bi][t * 32 + i];
            acc0 += p * sW[i * OUTD + j];
            acc1 += p * sW[i * OUTD + j + 64];
        }
        __syncthreads();
    }
    out[(b0 + bi) * OUTD + j]      = tanhf(acc0);
    out[(b0 + bi) * OUTD + j + 64] = tanhf(acc1);
}

extern "C" void kernel_launch(void* const* d_in, const int* in_sizes, int n_in,
                              void* d_out, int out_size) {
    const float* hidden = (const float*)d_in[0];   // (128, 2048, 256) f32
    const float* Wscore = (const float*)d_in[1];   // (256, 256) f32
    const float* Watt   = (const float*)d_in[2];   // (512, 128) f32
    float* out = (float*)d_out;                    // (128, 128) f32

    cudaFuncSetAttribute(k1_stream, cudaFuncAttributeMaxDynamicSharedMemorySize, SMEM_K1);

    k0_compute_v<<<dim3(BB / K0_BT, HH / K0_HT), 256>>>(hidden, Wscore);
    k1_stream<<<BB * NCHUNK, K1_THREADS, SMEM_K1>>>(hidden);
    k2_combine<<<16, 512>>>(hidden, Watt, out);
}